// round 5
// baseline (speedup 1.0000x reference)
#include <cuda_runtime.h>
#include <cuda_bf16.h>
#include <math.h>
#include <stdint.h>

#define DIMV   1024
#define HEADS  16
#define HD     64
#define BATCH  8
#define SEQ    1024
#define MTOT   (BATCH*SEQ)
#define SCALEF 0.125f

/* ------------------------------------------------------------------ */
/* bf16 hi/lo planes (static device scratch)                           */
/* ------------------------------------------------------------------ */
#define PLANE (BATCH*HEADS*SEQ*HD)          /* 8M */
__device__ __nv_bfloat16 g_xh[(size_t)MTOT*DIMV],  g_xl[(size_t)MTOT*DIMV];
__device__ __nv_bfloat16 g_wqh[3*DIMV*DIMV],       g_wql[3*DIMV*DIMV];
__device__ __nv_bfloat16 g_wph[DIMV*DIMV],         g_wpl[DIMV*DIMV];
__device__ __nv_bfloat16 g_qh[PLANE], g_ql[PLANE];
__device__ __nv_bfloat16 g_kh[PLANE], g_kl[PLANE];
__device__ __nv_bfloat16 g_vh[PLANE], g_vl[PLANE];
__device__ __nv_bfloat16 g_oh[(size_t)MTOT*DIMV],  g_ol[(size_t)MTOT*DIMV];

__device__ __forceinline__ uint32_t smem_u32(const void* p) {
    uint32_t a;
    asm("{ .reg .u64 t; cvta.to.shared.u64 t, %1; cvt.u32.u64 %0, t; }"
        : "=r"(a) : "l"(p));
    return a;
}
__device__ __forceinline__ void ldm_x4(uint32_t* r, uint32_t addr) {
    asm volatile("ldmatrix.sync.aligned.m8n8.x4.shared.b16 {%0,%1,%2,%3}, [%4];"
                 : "=r"(r[0]), "=r"(r[1]), "=r"(r[2]), "=r"(r[3]) : "r"(addr));
}
__device__ __forceinline__ void ldm_x4_t(uint32_t* r, uint32_t addr) {
    asm volatile("ldmatrix.sync.aligned.m8n8.x4.trans.shared.b16 {%0,%1,%2,%3}, [%4];"
                 : "=r"(r[0]), "=r"(r[1]), "=r"(r[2]), "=r"(r[3]) : "r"(addr));
}
__device__ __forceinline__ void mma_bf16(float* c, const uint32_t* a, const uint32_t* b) {
    asm volatile("mma.sync.aligned.m16n8k16.row.col.f32.bf16.bf16.f32 "
                 "{%0,%1,%2,%3}, {%4,%5,%6,%7}, {%8,%9}, {%0,%1,%2,%3};"
                 : "+f"(c[0]), "+f"(c[1]), "+f"(c[2]), "+f"(c[3])
                 : "r"(a[0]), "r"(a[1]), "r"(a[2]), "r"(a[3]), "r"(b[0]), "r"(b[1]));
}
__device__ __forceinline__ void cp16(uint32_t sm, const void* gm) {
    asm volatile("cp.async.cg.shared.global [%0], [%1], 16;" :: "r"(sm), "l"(gm));
}
#define CP_COMMIT() asm volatile("cp.async.commit_group;" ::: "memory")

/* ------------------------------------------------------------------ */
/* fp32 -> bf16 hi/lo split (elementwise, vectorized)                  */
/* ------------------------------------------------------------------ */
__global__ void __launch_bounds__(256) split_f32(
    const float* __restrict__ src, __nv_bfloat16* __restrict__ h,
    __nv_bfloat16* __restrict__ l, int n4)
{
    int i = blockIdx.x * blockDim.x + threadIdx.x;
    if (i >= n4) return;
    float4 v = *(const float4*)&src[(size_t)i * 4];
    __nv_bfloat162 h01 = __floats2bfloat162_rn(v.x, v.y);
    __nv_bfloat162 h23 = __floats2bfloat162_rn(v.z, v.w);
    __nv_bfloat162 l01 = __floats2bfloat162_rn(v.x - __bfloat162float(h01.x),
                                               v.y - __bfloat162float(h01.y));
    __nv_bfloat162 l23 = __floats2bfloat162_rn(v.z - __bfloat162float(h23.x),
                                               v.w - __bfloat162float(h23.y));
    *(uint2*)&h[(size_t)i * 4] = make_uint2(*(uint32_t*)&h01, *(uint32_t*)&h23);
    *(uint2*)&l[(size_t)i * 4] = make_uint2(*(uint32_t*)&l01, *(uint32_t*)&l23);
}

/* ------------------------------------------------------------------ */
/* GEMM v2: pre-split bf16 planes in, cp.async 2-stage pipeline.       */
/* C[M,N] = A*B^T (3-pass hi/lo). BM=BN=128, BK=32, 8 warps 2x4.       */
/* MODE 0: QKV scatter -> q/k/v planes (Q scaled). MODE 1: +bias fp32. */
/* ------------------------------------------------------------------ */
#define SP 40
#define PLB (128*SP*2)          /* plane bytes in smem: 10240 */
#define STAGE_B (4*PLB)         /* 40960 */
#define GSMEM (2*STAGE_B)       /* 81920 */

template<int MODE>
__global__ void __launch_bounds__(256, 2) gemm2(
    const __nv_bfloat16* __restrict__ Ah_, const __nv_bfloat16* __restrict__ Al_,
    const __nv_bfloat16* __restrict__ Bh, const __nv_bfloat16* __restrict__ Bl,
    int Nn, const float* __restrict__ bias, float* __restrict__ out)
{
    extern __shared__ char smraw[];
    const uint32_t s0 = smem_u32(smraw);

    const __nv_bfloat16* Ah = (MODE == 1) ? g_oh : Ah_;
    const __nv_bfloat16* Al = (MODE == 1) ? g_ol : Al_;

    const int tid  = threadIdx.x;
    const int lane = tid & 31;
    const int wid  = tid >> 5;
    const int wm   = wid >> 2;
    const int wn   = wid & 3;
    const int m0   = blockIdx.y * 128;
    const int n0   = blockIdx.x * 128;

    const int lrow = tid >> 1;           /* 0..127 */
    const int lcol = (tid & 1) * 16;     /* 0 / 16 */

    const int a_lrow = (lane & 7) + ((lane >> 3) & 1) * 8;
    const int a_lkof = (lane >> 4) * 8;
    const int b_lrow = (lane & 7) + (lane >> 4) * 8;
    const int b_lkof = ((lane >> 3) & 1) * 8;

    float acc[4][4][4];
#pragma unroll
    for (int i = 0; i < 4; i++)
#pragma unroll
        for (int j = 0; j < 4; j++)
#pragma unroll
            for (int r = 0; r < 4; r++) acc[i][j][r] = 0.f;

    /* stage loader: 8 x cp.async 16B */
    auto load_stage = [&](int s, int k0) {
        const uint32_t sb = s0 + s * STAGE_B + (uint32_t)(lrow * SP + lcol) * 2;
        const size_t ga = (size_t)(m0 + lrow) * DIMV + k0 + lcol;
        const size_t gb = (size_t)(n0 + lrow) * DIMV + k0 + lcol;
        cp16(sb + 0*PLB,      &Ah[ga]);  cp16(sb + 0*PLB + 16, &Ah[ga + 8]);
        cp16(sb + 1*PLB,      &Al[ga]);  cp16(sb + 1*PLB + 16, &Al[ga + 8]);
        cp16(sb + 2*PLB,      &Bh[gb]);  cp16(sb + 2*PLB + 16, &Bh[gb + 8]);
        cp16(sb + 3*PLB,      &Bl[gb]);  cp16(sb + 3*PLB + 16, &Bl[gb + 8]);
    };

    load_stage(0, 0);
    CP_COMMIT();

    for (int c = 0; c < DIMV / 32; c++) {
        if (c < DIMV / 32 - 1) {
            load_stage((c + 1) & 1, (c + 1) * 32);
            CP_COMMIT();
            asm volatile("cp.async.wait_group 1;" ::: "memory");
        } else {
            asm volatile("cp.async.wait_group 0;" ::: "memory");
        }
        __syncthreads();

        const uint32_t st  = s0 + (c & 1) * STAGE_B;
        const uint32_t uAh = st + 0*PLB, uAl = st + 1*PLB;
        const uint32_t uBh = st + 2*PLB, uBl = st + 3*PLB;

#pragma unroll
        for (int ks = 0; ks < 2; ks++) {
            const int kk = ks * 16;
            uint32_t bfh[2][4], bfl[2][4];
#pragma unroll
            for (int bi = 0; bi < 2; bi++) {
                uint32_t boff = (uint32_t)((wn * 32 + bi * 16 + b_lrow) * SP
                                           + kk + b_lkof) * 2;
                ldm_x4(bfh[bi], uBh + boff);
                ldm_x4(bfl[bi], uBl + boff);
            }
#pragma unroll
            for (int mi = 0; mi < 4; mi++) {
                uint32_t af_h[4], af_l[4];
                uint32_t aoff = (uint32_t)((wm * 64 + mi * 16 + a_lrow) * SP
                                           + kk + a_lkof) * 2;
                ldm_x4(af_h, uAh + aoff);
                ldm_x4(af_l, uAl + aoff);
#pragma unroll
                for (int ni = 0; ni < 4; ni++) {
                    const uint32_t* bh = &bfh[ni >> 1][(ni & 1) * 2];
                    const uint32_t* bl = &bfl[ni >> 1][(ni & 1) * 2];
                    mma_bf16(acc[mi][ni], af_h, bh);
                    mma_bf16(acc[mi][ni], af_h, bl);
                    mma_bf16(acc[mi][ni], af_l, bh);
                }
            }
        }
        __syncthreads();
    }

    /* epilogue */
    const int r_base = wm * 64 + (lane >> 2);
    const int c_base = wn * 32 + (lane & 3) * 2;
#pragma unroll
    for (int mi = 0; mi < 4; mi++) {
#pragma unroll
        for (int ni = 0; ni < 4; ni++) {
            int gcol = n0 + c_base + ni * 8;
#pragma unroll
            for (int half = 0; half < 2; half++) {
                int grow = m0 + r_base + mi * 16 + half * 8;
                float v0 = acc[mi][ni][half * 2 + 0];
                float v1 = acc[mi][ni][half * 2 + 1];
                if (MODE == 0) {
                    int qkv = gcol >> 10;
                    int hh  = (gcol >> 6) & 15;
                    int dd  = gcol & 63;
                    int b   = grow >> 10;
                    int sp  = grow & 1023;
                    size_t off = (((size_t)(b * HEADS + hh) * SEQ) + sp) * HD + dd;
                    if (qkv == 0) { v0 *= SCALEF; v1 *= SCALEF; }
                    __nv_bfloat16 h0 = __float2bfloat16_rn(v0);
                    __nv_bfloat16 h1 = __float2bfloat16_rn(v1);
                    __nv_bfloat16 l0 = __float2bfloat16_rn(v0 - __bfloat162float(h0));
                    __nv_bfloat16 l1 = __float2bfloat16_rn(v1 - __bfloat162float(h1));
                    __nv_bfloat16* ph = (qkv == 0) ? g_qh : (qkv == 1) ? g_kh : g_vh;
                    __nv_bfloat16* pl = (qkv == 0) ? g_ql : (qkv == 1) ? g_kl : g_vl;
                    *(__nv_bfloat162*)&ph[off] = __halves2bfloat162(h0, h1);
                    *(__nv_bfloat162*)&pl[off] = __halves2bfloat162(l0, l1);
                } else {
                    float2 bb = *(const float2*)&bias[gcol];
                    *(float2*)&out[(size_t)grow * Nn + gcol] =
                        make_float2(v0 + bb.x, v1 + bb.y);
                }
            }
        }
    }
}

/* ------------------------------------------------------------------ */
/* Tensor-core flash attention (round-4 proven), epilogue -> planes    */
/* ------------------------------------------------------------------ */
#define QP 72

__global__ void __launch_bounds__(256) attn_mma()
{
    extern __shared__ __nv_bfloat16 smb[];
    __nv_bfloat16* Qh = smb;
    __nv_bfloat16* Ql = Qh + 128 * QP;
    __nv_bfloat16* Kh = Ql + 128 * QP;
    __nv_bfloat16* Kl = Kh + 64 * QP;
    __nv_bfloat16* Vh = Kl + 64 * QP;
    __nv_bfloat16* Vl = Vh + 64 * QP;

    const uint32_t uQh = smem_u32(Qh), uQl = smem_u32(Ql);
    const uint32_t uKh = smem_u32(Kh), uKl = smem_u32(Kl);
    const uint32_t uVh = smem_u32(Vh), uVl = smem_u32(Vl);

    const int tid  = threadIdx.x;
    const int lane = tid & 31;
    const int wid  = tid >> 5;
    const int bh   = blockIdx.y;
    const int m0   = blockIdx.x * 128;

    const size_t pbase = (size_t)bh * SEQ * HD;
    const __nv_bfloat16* pqh = g_qh + pbase;
    const __nv_bfloat16* pql = g_ql + pbase;
    const __nv_bfloat16* pkh = g_kh + pbase;
    const __nv_bfloat16* pkl = g_kl + pbase;
    const __nv_bfloat16* pvh = g_vh + pbase;
    const __nv_bfloat16* pvl = g_vl + pbase;

#pragma unroll
    for (int t = 0; t < 8; t++) {
        int idx = t * 256 + tid;
        int row = idx >> 4;
        int g   = idx & 15;
        size_t go = (size_t)(m0 + row) * HD + g * 4;
        *(uint2*)&Qh[row * QP + g * 4] = *(const uint2*)&pqh[go];
        *(uint2*)&Ql[row * QP + g * 4] = *(const uint2*)&pql[go];
    }

    float o[8][4];
#pragma unroll
    for (int n = 0; n < 8; n++)
#pragma unroll
        for (int r = 0; r < 4; r++) o[n][r] = 0.f;
    float mrow[2] = {-1e30f, -1e30f};
    float lrow[2] = {0.f, 0.f};

    const int a_row = wid * 16 + (lane & 15);
    const int a_kof = (lane >> 4) * 8;
    const int b_row = (lane & 7) + (lane >> 4) * 8;
    const int b_kof = ((lane >> 3) & 1) * 8;
    const int v_key = ((lane >> 3) & 1) * 8 + (lane & 7);
    const int v_col = (lane >> 4) * 8;

    for (int c = 0; c < 16; c++) {
        const int key0 = c * 64;
        __syncthreads();
#pragma unroll
        for (int t = 0; t < 4; t++) {
            int idx = t * 256 + tid;
            int row = idx >> 4;
            int g   = idx & 15;
            size_t go = (size_t)(key0 + row) * HD + g * 4;
            uint32_t so = row * QP + g * 4;
            *(uint2*)&Kh[so] = *(const uint2*)&pkh[go];
            *(uint2*)&Kl[so] = *(const uint2*)&pkl[go];
            *(uint2*)&Vh[so] = *(const uint2*)&pvh[go];
            *(uint2*)&Vl[so] = *(const uint2*)&pvl[go];
        }
        __syncthreads();

        float s[8][4];
#pragma unroll
        for (int n = 0; n < 8; n++)
#pragma unroll
            for (int r = 0; r < 4; r++) s[n][r] = 0.f;

#pragma unroll
        for (int kk = 0; kk < 4; kk++) {
            uint32_t qhf[4], qlf[4];
            uint32_t aoff = (uint32_t)(a_row * QP + kk * 16 + a_kof) * 2;
            ldm_x4(qhf, uQh + aoff);
            ldm_x4(qlf, uQl + aoff);

            uint32_t kbh[4][4], kbl[4][4];
#pragma unroll
            for (int bi = 0; bi < 4; bi++) {
                uint32_t boff = (uint32_t)((bi * 16 + b_row) * QP + kk * 16 + b_kof) * 2;
                ldm_x4(kbh[bi], uKh + boff);
                ldm_x4(kbl[bi], uKl + boff);
            }
#pragma unroll
            for (int ni = 0; ni < 8; ni++) {
                const uint32_t* bhp = &kbh[ni >> 1][(ni & 1) * 2];
                const uint32_t* blp = &kbl[ni >> 1][(ni & 1) * 2];
                mma_bf16(s[ni], qhf, bhp);
                mma_bf16(s[ni], qhf, blp);
                mma_bf16(s[ni], qlf, bhp);
            }
        }

        float alpha[2];
#pragma unroll
        for (int r = 0; r < 2; r++) {
            float mx = -1e30f;
#pragma unroll
            for (int ni = 0; ni < 8; ni++)
                mx = fmaxf(mx, fmaxf(s[ni][r * 2], s[ni][r * 2 + 1]));
            mx = fmaxf(mx, __shfl_xor_sync(0xffffffffu, mx, 1));
            mx = fmaxf(mx, __shfl_xor_sync(0xffffffffu, mx, 2));
            float mnew = fmaxf(mrow[r], mx);
            alpha[r] = __expf(mrow[r] - mnew);
            mrow[r] = mnew;
            float ls = 0.f;
#pragma unroll
            for (int ni = 0; ni < 8; ni++) {
                s[ni][r * 2]     = __expf(s[ni][r * 2]     - mnew);
                s[ni][r * 2 + 1] = __expf(s[ni][r * 2 + 1] - mnew);
                ls += s[ni][r * 2] + s[ni][r * 2 + 1];
            }
            ls += __shfl_xor_sync(0xffffffffu, ls, 1);
            ls += __shfl_xor_sync(0xffffffffu, ls, 2);
            lrow[r] = lrow[r] * alpha[r] + ls;
#pragma unroll
            for (int ni = 0; ni < 8; ni++) {
                o[ni][r * 2]     *= alpha[r];
                o[ni][r * 2 + 1] *= alpha[r];
            }
        }

#pragma unroll
        for (int kk = 0; kk < 4; kk++) {
            uint32_t pha[4], pla[4];
#pragma unroll
            for (int q = 0; q < 4; q++) {
                float f0 = (q & 2) ? s[2 * kk + 1][(q & 1) * 2]     : s[2 * kk][(q & 1) * 2];
                float f1 = (q & 2) ? s[2 * kk + 1][(q & 1) * 2 + 1] : s[2 * kk][(q & 1) * 2 + 1];
                __nv_bfloat162 h2 = __floats2bfloat162_rn(f0, f1);
                __nv_bfloat162 l2 = __floats2bfloat162_rn(f0 - __bfloat162float(h2.x),
                                                          f1 - __bfloat162float(h2.y));
                pha[q] = *(uint32_t*)&h2;
                pla[q] = *(uint32_t*)&l2;
            }
            uint32_t vbh[4][4], vbl[4][4];
#pragma unroll
            for (int np = 0; np < 4; np++) {
                uint32_t voff = (uint32_t)((kk * 16 + v_key) * QP + np * 16 + v_col) * 2;
                ldm_x4_t(vbh[np], uVh + voff);
                ldm_x4_t(vbl[np], uVl + voff);
            }
#pragma unroll
            for (int ni = 0; ni < 8; ni++) {
                const uint32_t* bhp = &vbh[ni >> 1][(ni & 1) * 2];
                const uint32_t* blp = &vbl[ni >> 1][(ni & 1) * 2];
                mma_bf16(o[ni], pha, bhp);
                mma_bf16(o[ni], pha, blp);
                mma_bf16(o[ni], pla, bhp);
            }
        }
    }

    /* epilogue: normalize, split, write bf16 hi/lo planes [b,n,dim] */
    const int b = bh >> 4;
    const int h = bh & 15;
#pragma unroll
    for (int r = 0; r < 2; r++) {
        float inv = 1.f / lrow[r];
        int row = m0 + wid * 16 + (lane >> 2) + r * 8;
        size_t base = ((size_t)(b * SEQ + row)) * DIMV + h * HD + (lane & 3) * 2;
#pragma unroll
        for (int ni = 0; ni < 8; ni++) {
            float f0 = o[ni][r * 2] * inv;
            float f1 = o[ni][r * 2 + 1] * inv;
            __nv_bfloat162 h2 = __floats2bfloat162_rn(f0, f1);
            __nv_bfloat162 l2 = __floats2bfloat162_rn(f0 - __bfloat162float(h2.x),
                                                      f1 - __bfloat162float(h2.y));
            *(__nv_bfloat162*)&g_oh[base + ni * 8] = h2;
            *(__nv_bfloat162*)&g_ol[base + ni * 8] = l2;
        }
    }
}

/* ------------------------------------------------------------------ */
extern "C" void kernel_launch(void* const* d_in, const int* in_sizes, int n_in,
                              void* d_out, int out_size)
{
    const float* x = nullptr;
    const float* Wqkv = nullptr;
    const float* Wproj = nullptr;
    const float* bproj = nullptr;
    for (int i = 0; i < n_in; i++) {
        switch (in_sizes[i]) {
            case 8388608: x     = (const float*)d_in[i]; break;
            case 3145728: Wqkv  = (const float*)d_in[i]; break;
            case 1048576: Wproj = (const float*)d_in[i]; break;
            case 1024:    bproj = (const float*)d_in[i]; break;
            default: break;
        }
    }
    float* out = (float*)d_out;

    /* resolve device-global plane addresses */
    __nv_bfloat16 *xh, *xl, *wqh, *wql, *wph, *wpl;
    cudaGetSymbolAddress((void**)&xh,  g_xh);
    cudaGetSymbolAddress((void**)&xl,  g_xl);
    cudaGetSymbolAddress((void**)&wqh, g_wqh);
    cudaGetSymbolAddress((void**)&wql, g_wql);
    cudaGetSymbolAddress((void**)&wph, g_wph);
    cudaGetSymbolAddress((void**)&wpl, g_wpl);

    /* pre-split fp32 inputs into bf16 hi/lo planes */
    split_f32<<<(8388608/4 + 255)/256, 256>>>(x,     xh,  xl,  8388608/4);
    split_f32<<<(3145728/4 + 255)/256, 256>>>(Wqkv,  wqh, wql, 3145728/4);
    split_f32<<<(1048576/4 + 255)/256, 256>>>(Wproj, wph, wpl, 1048576/4);

    /* QKV GEMM (cp.async pipelined) -> q/k/v planes */
    {
        cudaFuncSetAttribute(gemm2<0>, cudaFuncAttributeMaxDynamicSharedMemorySize, GSMEM);
        dim3 grid(3 * DIMV / 128, MTOT / 128);
        gemm2<0><<<grid, 256, GSMEM>>>(xh, xl, wqh, wql, 3 * DIMV, nullptr, nullptr);
    }

    /* tensor-core attention -> o planes */
    {
        size_t smem = (size_t)(2 * 128 + 4 * 64) * QP * sizeof(__nv_bfloat16);
        cudaFuncSetAttribute(attn_mma, cudaFuncAttributeMaxDynamicSharedMemorySize,
                             (int)smem);
        dim3 grid(SEQ / 128, BATCH * HEADS);
        attn_mma<<<grid, 256, smem>>>();
    }

    /* projection GEMM + bias -> fp32 out */
    {
        cudaFuncSetAttribute(gemm2<1>, cudaFuncAttributeMaxDynamicSharedMemorySize, GSMEM);
        dim3 grid(DIMV / 128, MTOT / 128);
        gemm2<1><<<grid, 256, GSMEM>>>(nullptr, nullptr, wph, wpl, DIMV, bproj, out);
    }
    (void)out_size; (void)n_in;
}

// round 6
// speedup vs baseline: 1.0765x; 1.0765x over previous
#include <cuda_runtime.h>
#include <cuda_bf16.h>
#include <math.h>
#include <stdint.h>

#define DIMV   1024
#define HEADS  16
#define HD     64
#define BATCH  8
#define SEQ    1024
#define MTOT   (BATCH*SEQ)
#define SCALEF 0.125f

/* ------------------------------------------------------------------ */
/* bf16 hi/lo planes (static device scratch)                           */
/* ------------------------------------------------------------------ */
#define PLANE (BATCH*HEADS*SEQ*HD)
__device__ __nv_bfloat16 g_xh[(size_t)MTOT*DIMV],  g_xl[(size_t)MTOT*DIMV];
__device__ __nv_bfloat16 g_wqh[3*DIMV*DIMV],       g_wql[3*DIMV*DIMV];
__device__ __nv_bfloat16 g_wph[DIMV*DIMV],         g_wpl[DIMV*DIMV];
__device__ __nv_bfloat16 g_qh[PLANE], g_ql[PLANE];
__device__ __nv_bfloat16 g_kh[PLANE], g_kl[PLANE];
__device__ __nv_bfloat16 g_vh[PLANE], g_vl[PLANE];
__device__ __nv_bfloat16 g_oh[(size_t)MTOT*DIMV],  g_ol[(size_t)MTOT*DIMV];

__device__ __forceinline__ uint32_t smem_u32(const void* p) {
    uint32_t a;
    asm("{ .reg .u64 t; cvta.to.shared.u64 t, %1; cvt.u32.u64 %0, t; }"
        : "=r"(a) : "l"(p));
    return a;
}
__device__ __forceinline__ void ldm_x4(uint32_t* r, uint32_t addr) {
    asm volatile("ldmatrix.sync.aligned.m8n8.x4.shared.b16 {%0,%1,%2,%3}, [%4];"
                 : "=r"(r[0]), "=r"(r[1]), "=r"(r[2]), "=r"(r[3]) : "r"(addr));
}
__device__ __forceinline__ void ldm_x4_t(uint32_t* r, uint32_t addr) {
    asm volatile("ldmatrix.sync.aligned.m8n8.x4.trans.shared.b16 {%0,%1,%2,%3}, [%4];"
                 : "=r"(r[0]), "=r"(r[1]), "=r"(r[2]), "=r"(r[3]) : "r"(addr));
}
__device__ __forceinline__ void mma_bf16(float* c, const uint32_t* a, const uint32_t* b) {
    asm volatile("mma.sync.aligned.m16n8k16.row.col.f32.bf16.bf16.f32 "
                 "{%0,%1,%2,%3}, {%4,%5,%6,%7}, {%8,%9}, {%0,%1,%2,%3};"
                 : "+f"(c[0]), "+f"(c[1]), "+f"(c[2]), "+f"(c[3])
                 : "r"(a[0]), "r"(a[1]), "r"(a[2]), "r"(a[3]), "r"(b[0]), "r"(b[1]));
}

/* ------------------------------------------------------------------ */
/* fp32 -> bf16 hi/lo split                                            */
/* ------------------------------------------------------------------ */
__global__ void __launch_bounds__(256) split_f32(
    const float* __restrict__ src, __nv_bfloat16* __restrict__ h,
    __nv_bfloat16* __restrict__ l, int n4)
{
    int i = blockIdx.x * blockDim.x + threadIdx.x;
    if (i >= n4) return;
    float4 v = *(const float4*)&src[(size_t)i * 4];
    __nv_bfloat162 h01 = __floats2bfloat162_rn(v.x, v.y);
    __nv_bfloat162 h23 = __floats2bfloat162_rn(v.z, v.w);
    __nv_bfloat162 l01 = __floats2bfloat162_rn(v.x - __bfloat162float(h01.x),
                                               v.y - __bfloat162float(h01.y));
    __nv_bfloat162 l23 = __floats2bfloat162_rn(v.z - __bfloat162float(h23.x),
                                               v.w - __bfloat162float(h23.y));
    *(uint2*)&h[(size_t)i * 4] = make_uint2(*(uint32_t*)&h01, *(uint32_t*)&h23);
    *(uint2*)&l[(size_t)i * 4] = make_uint2(*(uint32_t*)&l01, *(uint32_t*)&l23);
}

/* ------------------------------------------------------------------ */
/* GEMM v3: bf16 planes in via plain LDG.128 (L1 path), single buffer, */
/* BM=BN=128, BK=32, 8 warps 2x4, 2 CTAs/SM. 3-pass hi/lo MMA.         */
/* MODE 0: QKV scatter -> q/k/v planes (Q scaled). MODE 1: +bias fp32. */
/* ------------------------------------------------------------------ */
#define SP 40

template<int MODE>
__global__ void __launch_bounds__(256, 2) gemm3(
    const __nv_bfloat16* __restrict__ Ah_, const __nv_bfloat16* __restrict__ Al_,
    const __nv_bfloat16* __restrict__ Bh, const __nv_bfloat16* __restrict__ Bl,
    int Nn, const float* __restrict__ bias, float* __restrict__ out)
{
    __shared__ __nv_bfloat16 sAh[128 * SP];
    __shared__ __nv_bfloat16 sAl[128 * SP];
    __shared__ __nv_bfloat16 sBh[128 * SP];
    __shared__ __nv_bfloat16 sBl[128 * SP];

    const __nv_bfloat16* Ah = (MODE == 1) ? g_oh : Ah_;
    const __nv_bfloat16* Al = (MODE == 1) ? g_ol : Al_;

    const int tid  = threadIdx.x;
    const int lane = tid & 31;
    const int wid  = tid >> 5;
    const int wm   = wid >> 2;
    const int wn   = wid & 3;
    const int m0   = blockIdx.y * 128;
    const int n0   = blockIdx.x * 128;

    const uint32_t uAh = smem_u32(sAh);
    const uint32_t uAl = smem_u32(sAl);
    const uint32_t uBh = smem_u32(sBh);
    const uint32_t uBl = smem_u32(sBl);

    const int a_lrow = (lane & 7) + ((lane >> 3) & 1) * 8;
    const int a_lkof = (lane >> 4) * 8;
    const int b_lrow = (lane & 7) + (lane >> 4) * 8;
    const int b_lkof = ((lane >> 3) & 1) * 8;

    float acc[4][4][4];
#pragma unroll
    for (int i = 0; i < 4; i++)
#pragma unroll
        for (int j = 0; j < 4; j++)
#pragma unroll
            for (int r = 0; r < 4; r++) acc[i][j][r] = 0.f;

    /* load indexing: per plane 128 rows x 32 bf16 = 512 x 16B chunks.
       thread handles rows r0 and r0+64 at 16B col c8.                  */
    const int r0 = tid >> 2;           /* 0..63 */
    const int c8 = (tid & 3) * 8;      /* bf16 col: 0,8,16,24 */
    const uint32_t so0 = (uint32_t)(r0 * SP + c8) * 2;
    const uint32_t so1 = so0 + (uint32_t)(64 * SP) * 2;

    for (int c = 0; c < DIMV / 32; c++) {
        const int k0 = c * 32;
        const size_t ga = (size_t)(m0 + r0) * DIMV + k0 + c8;
        const size_t gb = (size_t)(n0 + r0) * DIMV + k0 + c8;
        const size_t gs = (size_t)64 * DIMV;

        /* issue all 8 global loads first (latency overlaps sync below) */
        uint4 vah0 = *(const uint4*)&Ah[ga];
        uint4 vah1 = *(const uint4*)&Ah[ga + gs];
        uint4 val0 = *(const uint4*)&Al[ga];
        uint4 val1 = *(const uint4*)&Al[ga + gs];
        uint4 vbh0 = *(const uint4*)&Bh[gb];
        uint4 vbh1 = *(const uint4*)&Bh[gb + gs];
        uint4 vbl0 = *(const uint4*)&Bl[gb];
        uint4 vbl1 = *(const uint4*)&Bl[gb + gs];

        __syncthreads();   /* previous MMA phase done reading smem */

        *(uint4*)((char*)sAh + so0) = vah0;
        *(uint4*)((char*)sAh + so1) = vah1;
        *(uint4*)((char*)sAl + so0) = val0;
        *(uint4*)((char*)sAl + so1) = val1;
        *(uint4*)((char*)sBh + so0) = vbh0;
        *(uint4*)((char*)sBh + so1) = vbh1;
        *(uint4*)((char*)sBl + so0) = vbl0;
        *(uint4*)((char*)sBl + so1) = vbl1;
        __syncthreads();

#pragma unroll
        for (int ks = 0; ks < 2; ks++) {
            const int kk = ks * 16;
            uint32_t bfh[2][4], bfl[2][4];
#pragma unroll
            for (int bi = 0; bi < 2; bi++) {
                uint32_t boff = (uint32_t)((wn * 32 + bi * 16 + b_lrow) * SP
                                           + kk + b_lkof) * 2;
                ldm_x4(bfh[bi], uBh + boff);
                ldm_x4(bfl[bi], uBl + boff);
            }
#pragma unroll
            for (int mi = 0; mi < 4; mi++) {
                uint32_t af_h[4], af_l[4];
                uint32_t aoff = (uint32_t)((wm * 64 + mi * 16 + a_lrow) * SP
                                           + kk + a_lkof) * 2;
                ldm_x4(af_h, uAh + aoff);
                ldm_x4(af_l, uAl + aoff);
#pragma unroll
                for (int ni = 0; ni < 4; ni++) {
                    const uint32_t* bh = &bfh[ni >> 1][(ni & 1) * 2];
                    const uint32_t* bl = &bfl[ni >> 1][(ni & 1) * 2];
                    mma_bf16(acc[mi][ni], af_h, bh);
                    mma_bf16(acc[mi][ni], af_h, bl);
                    mma_bf16(acc[mi][ni], af_l, bh);
                }
            }
        }
    }

    /* epilogue */
    const int r_base = wm * 64 + (lane >> 2);
    const int c_base = wn * 32 + (lane & 3) * 2;
#pragma unroll
    for (int mi = 0; mi < 4; mi++) {
#pragma unroll
        for (int ni = 0; ni < 4; ni++) {
            int gcol = n0 + c_base + ni * 8;
#pragma unroll
            for (int half = 0; half < 2; half++) {
                int grow = m0 + r_base + mi * 16 + half * 8;
                float v0 = acc[mi][ni][half * 2 + 0];
                float v1 = acc[mi][ni][half * 2 + 1];
                if (MODE == 0) {
                    int qkv = gcol >> 10;
                    int hh  = (gcol >> 6) & 15;
                    int dd  = gcol & 63;
                    int b   = grow >> 10;
                    int sp  = grow & 1023;
                    size_t off = (((size_t)(b * HEADS + hh) * SEQ) + sp) * HD + dd;
                    if (qkv == 0) { v0 *= SCALEF; v1 *= SCALEF; }
                    __nv_bfloat16 h0 = __float2bfloat16_rn(v0);
                    __nv_bfloat16 h1 = __float2bfloat16_rn(v1);
                    __nv_bfloat16 l0 = __float2bfloat16_rn(v0 - __bfloat162float(h0));
                    __nv_bfloat16 l1 = __float2bfloat16_rn(v1 - __bfloat162float(h1));
                    __nv_bfloat16* ph = (qkv == 0) ? g_qh : (qkv == 1) ? g_kh : g_vh;
                    __nv_bfloat16* pl = (qkv == 0) ? g_ql : (qkv == 1) ? g_kl : g_vl;
                    *(__nv_bfloat162*)&ph[off] = __halves2bfloat162(h0, h1);
                    *(__nv_bfloat162*)&pl[off] = __halves2bfloat162(l0, l1);
                } else {
                    float2 bb = *(const float2*)&bias[gcol];
                    *(float2*)&out[(size_t)grow * Nn + gcol] =
                        make_float2(v0 + bb.x, v1 + bb.y);
                }
            }
        }
    }
}

/* ------------------------------------------------------------------ */
/* Tensor-core flash attention (round-4/5 proven), epilogue -> planes  */
/* ------------------------------------------------------------------ */
#define QP 72

__global__ void __launch_bounds__(256) attn_mma()
{
    extern __shared__ __nv_bfloat16 smb[];
    __nv_bfloat16* Qh = smb;
    __nv_bfloat16* Ql = Qh + 128 * QP;
    __nv_bfloat16* Kh = Ql + 128 * QP;
    __nv_bfloat16* Kl = Kh + 64 * QP;
    __nv_bfloat16* Vh = Kl + 64 * QP;
    __nv_bfloat16* Vl = Vh + 64 * QP;

    const uint32_t uQh = smem_u32(Qh), uQl = smem_u32(Ql);
    const uint32_t uKh = smem_u32(Kh), uKl = smem_u32(Kl);
    const uint32_t uVh = smem_u32(Vh), uVl = smem_u32(Vl);

    const int tid  = threadIdx.x;
    const int lane = tid & 31;
    const int wid  = tid >> 5;
    const int bh   = blockIdx.y;
    const int m0   = blockIdx.x * 128;

    const size_t pbase = (size_t)bh * SEQ * HD;
    const __nv_bfloat16* pqh = g_qh + pbase;
    const __nv_bfloat16* pql = g_ql + pbase;
    const __nv_bfloat16* pkh = g_kh + pbase;
    const __nv_bfloat16* pkl = g_kl + pbase;
    const __nv_bfloat16* pvh = g_vh + pbase;
    const __nv_bfloat16* pvl = g_vl + pbase;

#pragma unroll
    for (int t = 0; t < 8; t++) {
        int idx = t * 256 + tid;
        int row = idx >> 4;
        int g   = idx & 15;
        size_t go = (size_t)(m0 + row) * HD + g * 4;
        *(uint2*)&Qh[row * QP + g * 4] = *(const uint2*)&pqh[go];
        *(uint2*)&Ql[row * QP + g * 4] = *(const uint2*)&pql[go];
    }

    float o[8][4];
#pragma unroll
    for (int n = 0; n < 8; n++)
#pragma unroll
        for (int r = 0; r < 4; r++) o[n][r] = 0.f;
    float mrow[2] = {-1e30f, -1e30f};
    float lrow[2] = {0.f, 0.f};

    const int a_row = wid * 16 + (lane & 15);
    const int a_kof = (lane >> 4) * 8;
    const int b_row = (lane & 7) + (lane >> 4) * 8;
    const int b_kof = ((lane >> 3) & 1) * 8;
    const int v_key = ((lane >> 3) & 1) * 8 + (lane & 7);
    const int v_col = (lane >> 4) * 8;

    for (int c = 0; c < 16; c++) {
        const int key0 = c * 64;
        __syncthreads();
#pragma unroll
        for (int t = 0; t < 4; t++) {
            int idx = t * 256 + tid;
            int row = idx >> 4;
            int g   = idx & 15;
            size_t go = (size_t)(key0 + row) * HD + g * 4;
            uint32_t so = row * QP + g * 4;
            *(uint2*)&Kh[so] = *(const uint2*)&pkh[go];
            *(uint2*)&Kl[so] = *(const uint2*)&pkl[go];
            *(uint2*)&Vh[so] = *(const uint2*)&pvh[go];
            *(uint2*)&Vl[so] = *(const uint2*)&pvl[go];
        }
        __syncthreads();

        float s[8][4];
#pragma unroll
        for (int n = 0; n < 8; n++)
#pragma unroll
            for (int r = 0; r < 4; r++) s[n][r] = 0.f;

#pragma unroll
        for (int kk = 0; kk < 4; kk++) {
            uint32_t qhf[4], qlf[4];
            uint32_t aoff = (uint32_t)(a_row * QP + kk * 16 + a_kof) * 2;
            ldm_x4(qhf, uQh + aoff);
            ldm_x4(qlf, uQl + aoff);

            uint32_t kbh[4][4], kbl[4][4];
#pragma unroll
            for (int bi = 0; bi < 4; bi++) {
                uint32_t boff = (uint32_t)((bi * 16 + b_row) * QP + kk * 16 + b_kof) * 2;
                ldm_x4(kbh[bi], uKh + boff);
                ldm_x4(kbl[bi], uKl + boff);
            }
#pragma unroll
            for (int ni = 0; ni < 8; ni++) {
                const uint32_t* bhp = &kbh[ni >> 1][(ni & 1) * 2];
                const uint32_t* blp = &kbl[ni >> 1][(ni & 1) * 2];
                mma_bf16(s[ni], qhf, bhp);
                mma_bf16(s[ni], qhf, blp);
                mma_bf16(s[ni], qlf, bhp);
            }
        }

        float alpha[2];
#pragma unroll
        for (int r = 0; r < 2; r++) {
            float mx = -1e30f;
#pragma unroll
            for (int ni = 0; ni < 8; ni++)
                mx = fmaxf(mx, fmaxf(s[ni][r * 2], s[ni][r * 2 + 1]));
            mx = fmaxf(mx, __shfl_xor_sync(0xffffffffu, mx, 1));
            mx = fmaxf(mx, __shfl_xor_sync(0xffffffffu, mx, 2));
            float mnew = fmaxf(mrow[r], mx);
            alpha[r] = __expf(mrow[r] - mnew);
            mrow[r] = mnew;
            float ls = 0.f;
#pragma unroll
            for (int ni = 0; ni < 8; ni++) {
                s[ni][r * 2]     = __expf(s[ni][r * 2]     - mnew);
                s[ni][r * 2 + 1] = __expf(s[ni][r * 2 + 1] - mnew);
                ls += s[ni][r * 2] + s[ni][r * 2 + 1];
            }
            ls += __shfl_xor_sync(0xffffffffu, ls, 1);
            ls += __shfl_xor_sync(0xffffffffu, ls, 2);
            lrow[r] = lrow[r] * alpha[r] + ls;
#pragma unroll
            for (int ni = 0; ni < 8; ni++) {
                o[ni][r * 2]     *= alpha[r];
                o[ni][r * 2 + 1] *= alpha[r];
            }
        }

#pragma unroll
        for (int kk = 0; kk < 4; kk++) {
            uint32_t pha[4], pla[4];
#pragma unroll
            for (int q = 0; q < 4; q++) {
                float f0 = (q & 2) ? s[2 * kk + 1][(q & 1) * 2]     : s[2 * kk][(q & 1) * 2];
                float f1 = (q & 2) ? s[2 * kk + 1][(q & 1) * 2 + 1] : s[2 * kk][(q & 1) * 2 + 1];
                __nv_bfloat162 h2 = __floats2bfloat162_rn(f0, f1);
                __nv_bfloat162 l2 = __floats2bfloat162_rn(f0 - __bfloat162float(h2.x),
                                                          f1 - __bfloat162float(h2.y));
                pha[q] = *(uint32_t*)&h2;
                pla[q] = *(uint32_t*)&l2;
            }
            uint32_t vbh[4][4], vbl[4][4];
#pragma unroll
            for (int np = 0; np < 4; np++) {
                uint32_t voff = (uint32_t)((kk * 16 + v_key) * QP + np * 16 + v_col) * 2;
                ldm_x4_t(vbh[np], uVh + voff);
                ldm_x4_t(vbl[np], uVl + voff);
            }
#pragma unroll
            for (int ni = 0; ni < 8; ni++) {
                const uint32_t* bhp = &vbh[ni >> 1][(ni & 1) * 2];
                const uint32_t* blp = &vbl[ni >> 1][(ni & 1) * 2];
                mma_bf16(o[ni], pha, bhp);
                mma_bf16(o[ni], pha, blp);
                mma_bf16(o[ni], pla, bhp);
            }
        }
    }

    /* epilogue: normalize, split, write bf16 hi/lo planes [b,n,dim] */
    const int b = bh >> 4;
    const int h = bh & 15;
#pragma unroll
    for (int r = 0; r < 2; r++) {
        float inv = 1.f / lrow[r];
        int row = m0 + wid * 16 + (lane >> 2) + r * 8;
        size_t base = ((size_t)(b * SEQ + row)) * DIMV + h * HD + (lane & 3) * 2;
#pragma unroll
        for (int ni = 0; ni < 8; ni++) {
            float f0 = o[ni][r * 2] * inv;
            float f1 = o[ni][r * 2 + 1] * inv;
            __nv_bfloat162 h2 = __floats2bfloat162_rn(f0, f1);
            __nv_bfloat162 l2 = __floats2bfloat162_rn(f0 - __bfloat162float(h2.x),
                                                      f1 - __bfloat162float(h2.y));
            *(__nv_bfloat162*)&g_oh[base + ni * 8] = h2;
            *(__nv_bfloat162*)&g_ol[base + ni * 8] = l2;
        }
    }
}

/* ------------------------------------------------------------------ */
extern "C" void kernel_launch(void* const* d_in, const int* in_sizes, int n_in,
                              void* d_out, int out_size)
{
    const float* x = nullptr;
    const float* Wqkv = nullptr;
    const float* Wproj = nullptr;
    const float* bproj = nullptr;
    for (int i = 0; i < n_in; i++) {
        switch (in_sizes[i]) {
            case 8388608: x     = (const float*)d_in[i]; break;
            case 3145728: Wqkv  = (const float*)d_in[i]; break;
            case 1048576: Wproj = (const float*)d_in[i]; break;
            case 1024:    bproj = (const float*)d_in[i]; break;
            default: break;
        }
    }
    float* out = (float*)d_out;

    __nv_bfloat16 *xh, *xl, *wqh, *wql, *wph, *wpl;
    cudaGetSymbolAddress((void**)&xh,  g_xh);
    cudaGetSymbolAddress((void**)&xl,  g_xl);
    cudaGetSymbolAddress((void**)&wqh, g_wqh);
    cudaGetSymbolAddress((void**)&wql, g_wql);
    cudaGetSymbolAddress((void**)&wph, g_wph);
    cudaGetSymbolAddress((void**)&wpl, g_wpl);

    /* pre-split fp32 inputs into bf16 hi/lo planes */
    split_f32<<<(8388608/4 + 255)/256, 256>>>(x,     xh,  xl,  8388608/4);
    split_f32<<<(3145728/4 + 255)/256, 256>>>(Wqkv,  wqh, wql, 3145728/4);
    split_f32<<<(1048576/4 + 255)/256, 256>>>(Wproj, wph, wpl, 1048576/4);

    /* QKV GEMM -> q/k/v planes */
    {
        dim3 grid(3 * DIMV / 128, MTOT / 128);
        gemm3<0><<<grid, 256>>>(xh, xl, wqh, wql, 3 * DIMV, nullptr, nullptr);
    }

    /* tensor-core attention -> o planes */
    {
        size_t smem = (size_t)(2 * 128 + 4 * 64) * QP * sizeof(__nv_bfloat16);
        cudaFuncSetAttribute(attn_mma, cudaFuncAttributeMaxDynamicSharedMemorySize,
                             (int)smem);
        dim3 grid(SEQ / 128, BATCH * HEADS);
        attn_mma<<<grid, 256, smem>>>();
    }

    /* projection GEMM + bias -> fp32 out */
    {
        dim3 grid(DIMV / 128, MTOT / 128);
        gemm3<1><<<grid, 256>>>(nullptr, nullptr, wph, wpl, DIMV, bproj, out);
    }
    (void)out_size; (void)n_in;
}